// round 4
// baseline (speedup 1.0000x reference)
#include <cuda_runtime.h>
#include <cuda_bf16.h>
#include <math.h>

// Problem constants (fixed by setup_inputs)
#define NF   1024      // features (rows of A)
#define NN   2048      // nodes (cols of A)
#define DIM  64
#define K12  768       // 12*dim
#define NFEAT 256      // 4*dim
#define EPS_F 1e-6f
#define LN_EPS_F 1e-5f

#define GRID 148       // <= SM count: all blocks co-resident -> safe grid barrier
#define TPB  256

// Device scratch (no allocations allowed)
__device__ unsigned int g_mask[NN * 32];        // 256 KB
__device__ float        g_feat[NN * NFEAT];     // 2 MB
__device__ float        g_logdeg[NN];
__device__ float        g_bsum[32];
__device__ float        g_bcnt[32];
__device__ float        g_Wt[K12 * DIM];        // W transposed (768, 64)

// Grid barrier state (persists across graph replays; sense-reversal via gen)
__device__ int                   g_bar_cnt;     // static-init 0
__device__ volatile unsigned int g_bar_gen;     // static-init 0

__device__ __forceinline__ void grid_barrier() {
    __syncthreads();
    if (threadIdx.x == 0) {
        unsigned int gen = g_bar_gen;           // must read BEFORE arrival
        __threadfence();                        // release: make phase writes visible
        if (atomicAdd(&g_bar_cnt, 1) == GRID - 1) {
            g_bar_cnt = 0;
            __threadfence();
            g_bar_gen = gen + 1;                // release the others
        } else {
            while (g_bar_gen == gen) { }        // spin (volatile)
        }
    }
    __syncthreads();
}

// ---------------------------------------------------------------------------
// One persistent kernel: phase A (masks + W^T + zero accums) -> barrier ->
// phase B (per-node stats + batch log-deg atomics) -> barrier ->
// phase C (fused scale-expansion GEMM + bias + LayerNorm + ReLU).
// Dynamic smem (phase C): featS4 64 KB + wS 24 KB.
// ---------------------------------------------------------------------------
#define NPB 16           // nodes per C-group
#define ICH 32           // i chunk -> 96 Wt rows staged (24 KB)
#define K4_SMEM ((NPB * NFEAT * 4 + 3 * ICH * DIM) * 4)

__global__ void __launch_bounds__(TPB, 1)
fused_all(const float* __restrict__ A,
          const float* __restrict__ x,
          const float* __restrict__ W,
          const float* __restrict__ bias,
          const float* __restrict__ gamma,
          const float* __restrict__ beta,
          const int*   __restrict__ b_n,
          float* __restrict__ out) {
    extern __shared__ float smemBuf[];          // 88 KB dynamic (phase C)

    // static smem for phase B + C epilogue (coexists with dynamic)
    __shared__ unsigned short sList[4][1024];
    __shared__ int   sCnt[4];
    __shared__ float scS[NPB * 2];
    __shared__ float redS[NPB][2][2];

    const int t   = threadIdx.x;
    const int tid = blockIdx.x * TPB + t;       // 0 .. 37887

    // ---------------- Phase A ----------------
    if (tid < 32) { g_bsum[tid] = 0.0f; g_bcnt[tid] = 0.0f; }

    // adjacency bitmasks: item m -> (n, word); consecutive tid -> consecutive n
    for (int m = tid; m < NN * 32; m += GRID * TPB) {
        int n = m & (NN - 1);
        int w = m >> 11;
        unsigned msk = 0;
#pragma unroll
        for (int r = 0; r < 32; r++) {
            if (A[(w * 32 + r) * NN + n] != 0.0f) msk |= (1u << r);
        }
        g_mask[n * 32 + w] = msk;
    }

    // W transpose (49152 elements)
    for (int idx = tid; idx < K12 * DIM; idx += GRID * TPB) {
        int d = idx / K12;
        int k = idx - d * K12;
        g_Wt[k * DIM + d] = W[idx];
    }

    grid_barrier();

    // ---------------- Phase B ----------------
    {
        int sub = t >> 6;       // node-within-group 0..3
        int d   = t & 63;
        for (int grp = blockIdx.x; grp < NN / 4; grp += GRID) {
            int n = grp * 4 + sub;

            if (d == 0) sCnt[sub] = 0;
            __syncthreads();

            if (d < 32) {
                unsigned m = g_mask[n * 32 + d];
                int base = d * 32;
                while (m) {
                    int b = __ffs(m) - 1;
                    m &= m - 1;
                    int pos = atomicAdd(&sCnt[sub], 1);
                    sList[sub][pos] = (unsigned short)(base + b);
                }
            }
            __syncthreads();

            int cnt = sCnt[sub];
            float s = 0.0f, sq = 0.0f;
            float mn = INFINITY, mx = -INFINITY;

            int j = 0;
            for (; j + 4 <= cnt; j += 4) {
                int f0 = sList[sub][j],     f1 = sList[sub][j + 1];
                int f2 = sList[sub][j + 2], f3 = sList[sub][j + 3];
                float x0 = x[f0 * DIM + d];
                float x1 = x[f1 * DIM + d];
                float x2 = x[f2 * DIM + d];
                float x3 = x[f3 * DIM + d];
                s  += (x0 + x1) + (x2 + x3);
                sq += (x0 * x0 + x1 * x1) + (x2 * x2 + x3 * x3);
                mn = fminf(mn, fminf(fminf(x0, x1), fminf(x2, x3)));
                mx = fmaxf(mx, fmaxf(fmaxf(x0, x1), fmaxf(x2, x3)));
            }
            for (; j < cnt; j++) {
                int f = sList[sub][j];
                float xv = x[f * DIM + d];
                s += xv; sq += xv * xv;
                mn = fminf(mn, xv); mx = fmaxf(mx, xv);
            }

            float deg  = (float)cnt + 1.0f;
            float mean = s / deg;
            float var  = sq / deg - mean * mean;
            float sd   = sqrtf(fmaxf(var, EPS_F));

            g_feat[n * NFEAT +           d] = mean;
            g_feat[n * NFEAT +  DIM    + d] = mn;
            g_feat[n * NFEAT + 2 * DIM + d] = mx;
            g_feat[n * NFEAT + 3 * DIM + d] = sd;
            if (d == 0) {
                float ld = logf(deg);
                g_logdeg[n] = ld;
                int b = b_n[n];
                atomicAdd(&g_bsum[b], ld);
                atomicAdd(&g_bcnt[b], 1.0f);
            }
            __syncthreads();
        }
    }

    grid_barrier();

    // ---------------- Phase C ----------------
    {
        float* featS4 = smemBuf;                       // NPB*NFEAT*4 floats
        float* wS     = smemBuf + NPB * NFEAT * 4;     // 3*ICH*DIM floats

        int d = t & 63;
        int g = t >> 6;

        for (int grp = blockIdx.x; grp < NN / NPB; grp += GRID) {
            int nb = grp * NPB;

            if (t < NPB) {
                int n = nb + t;
                int b = b_n[n];
                float ms = g_bsum[b] / fmaxf(g_bcnt[b], EPS_F);
                float sc = g_logdeg[n] / fmaxf(ms, EPS_F);
                scS[t * 2]     = sc;
                scS[t * 2 + 1] = 1.0f / fmaxf(sc, EPS_F);
            }
            __syncthreads();

            // prescale features into shared: float4 (fv, fv*sc, fv*inv, 0)
            for (int k = t; k < NPB * NFEAT; k += TPB) {
                int nl = k >> 8;
                float fv  = g_feat[nb * NFEAT + k];
                float sc  = scS[nl * 2];
                float inv = scS[nl * 2 + 1];
                reinterpret_cast<float4*>(featS4)[k] = make_float4(fv, fv * sc, fv * inv, 0.0f);
            }

            float acc[4] = {0.f, 0.f, 0.f, 0.f};

            for (int c = 0; c < NFEAT / ICH; c++) {
                __syncthreads();
                for (int k = t; k < 3 * ICH * DIM; k += TPB)
                    wS[k] = g_Wt[c * (3 * ICH * DIM) + k];
                __syncthreads();

#pragma unroll 4
                for (int il = 0; il < ICH; il++) {
                    float w0 = wS[(3 * il    ) * DIM + d];
                    float w1 = wS[(3 * il + 1) * DIM + d];
                    float w2 = wS[(3 * il + 2) * DIM + d];
                    int i = c * ICH + il;
#pragma unroll
                    for (int q = 0; q < 4; q++) {
                        float4 f = reinterpret_cast<const float4*>(featS4)[(g * 4 + q) * NFEAT + i];
                        acc[q] = fmaf(f.x, w0, fmaf(f.y, w1, fmaf(f.z, w2, acc[q])));
                    }
                }
            }

            // bias + LayerNorm + ReLU
            float bv = bias[d];
            float gv = gamma[d];
            float bt = beta[d];
            int wg = (t >> 5) & 1;

            float h[4];
#pragma unroll
            for (int q = 0; q < 4; q++) {
                h[q] = acc[q] + bv;
                float s1 = h[q];
                float s2 = h[q] * h[q];
#pragma unroll
                for (int off = 16; off > 0; off >>= 1) {
                    s1 += __shfl_xor_sync(0xffffffffu, s1, off);
                    s2 += __shfl_xor_sync(0xffffffffu, s2, off);
                }
                if ((t & 31) == 0) {
                    int nl = g * 4 + q;
                    redS[nl][wg][0] = s1;
                    redS[nl][wg][1] = s2;
                }
            }
            __syncthreads();

#pragma unroll
            for (int q = 0; q < 4; q++) {
                int nl = g * 4 + q;
                float tot  = redS[nl][0][0] + redS[nl][1][0];
                float tot2 = redS[nl][0][1] + redS[nl][1][1];
                float mu  = tot * (1.0f / DIM);
                float var = tot2 * (1.0f / DIM) - mu * mu;
                float o = (h[q] - mu) * rsqrtf(var + LN_EPS_F) * gv + bt;
                out[(nb + nl) * DIM + d] = fmaxf(o, 0.0f);
            }
            __syncthreads();
        }
    }
}

// ---------------------------------------------------------------------------
extern "C" void kernel_launch(void* const* d_in, const int* in_sizes, int n_in,
                              void* d_out, int out_size) {
    const float* A     = (const float*)d_in[0];   // (1024, 2048)
    const float* x     = (const float*)d_in[1];   // (1024, 64)
    const float* W     = (const float*)d_in[2];   // (64, 768)
    const float* bias  = (const float*)d_in[3];   // (64)
    const float* gamma = (const float*)d_in[4];   // (64)
    const float* beta  = (const float*)d_in[5];   // (64)
    const int*   b_n   = (const int*)d_in[6];     // (2048)
    float* out = (float*)d_out;                   // (2048, 64)

    static bool attrSet = false;
    if (!attrSet) {
        cudaFuncSetAttribute(fused_all, cudaFuncAttributeMaxDynamicSharedMemorySize, K4_SMEM);
        attrSet = true;
    }

    fused_all<<<GRID, TPB, K4_SMEM>>>(A, x, W, bias, gamma, beta, b_n, out);
}

// round 5
// speedup vs baseline: 1.5316x; 1.5316x over previous
#include <cuda_runtime.h>
#include <cuda_bf16.h>
#include <math.h>

// Problem constants (fixed by setup_inputs)
#define NF   1024      // features (rows of A)
#define NN   2048      // nodes (cols of A)
#define DIM  64
#define K12  768       // 12*dim
#define NFEAT 256      // 4*dim
#define EPS_F 1e-6f
#define LN_EPS_F 1e-5f

#define GRID 148       // <= SM count: all blocks co-resident -> safe grid barrier
#define TPB  512

#define NPB 16         // nodes per phase-C group
#define ICH 32         // i-chunk (32 feature rows -> 96 Wt rows per half-chunk)

// Dynamic smem layout (floats)
#define FEATT_OFF  0                         // featT[256][16]            16 KB
#define WS_OFF     4096                      // wS[2][3*ICH*DIM]          48 KB
#define SPART_OFF  (4096 + 2 * 3 * ICH * DIM)// sPart[2][16][3][64]       24 KB
#define DYN_FLOATS (SPART_OFF + 2 * NPB * 3 * DIM)
#define DYN_BYTES  (DYN_FLOATS * 4)

// Device scratch (no allocations allowed)
__device__ unsigned int g_mask[NN * 32];        // 256 KB
__device__ float        g_feat[NN * NFEAT];     // 2 MB   [node][mean|min|max|std]
__device__ float        g_logdeg[NN];
__device__ float        g_bsum[32];
__device__ float        g_bcnt[32];
__device__ float        g_Wt[K12 * DIM];        // W transposed (768, 64)

// Grid barrier (sense-reversal; state persists across graph replays)
__device__ int                   g_bar_cnt;
__device__ volatile unsigned int g_bar_gen;

__device__ __forceinline__ void grid_barrier() {
    __syncthreads();
    if (threadIdx.x == 0) {
        unsigned int gen = g_bar_gen;
        __threadfence();
        if (atomicAdd(&g_bar_cnt, 1) == GRID - 1) {
            g_bar_cnt = 0;
            __threadfence();
            g_bar_gen = gen + 1;
        } else {
            while (g_bar_gen == gen) { }
        }
    }
    __syncthreads();
}

__global__ void __launch_bounds__(TPB, 1)
fused_all(const float* __restrict__ A,
          const float* __restrict__ x,
          const float* __restrict__ W,
          const float* __restrict__ bias,
          const float* __restrict__ gamma,
          const float* __restrict__ beta,
          const int*   __restrict__ b_n,
          float* __restrict__ out) {
    extern __shared__ float smemBuf[];          // DYN_BYTES

    __shared__ int sCnt[8];

    const int t   = threadIdx.x;
    const int tid = blockIdx.x * TPB + t;

    // ---------------- Phase A: masks + W^T + zero accumulators ----------------
    if (tid < 32) { g_bsum[tid] = 0.0f; g_bcnt[tid] = 0.0f; }

    for (int m = tid; m < NN * 32; m += GRID * TPB) {
        int n = m & (NN - 1);
        int w = m >> 11;
        unsigned msk = 0;
#pragma unroll
        for (int r = 0; r < 32; r++) {
            if (A[(w * 32 + r) * NN + n] != 0.0f) msk |= (1u << r);
        }
        g_mask[n * 32 + w] = msk;
    }

    for (int idx = tid; idx < K12 * DIM; idx += GRID * TPB) {
        int d = idx / K12;
        int k = idx - d * K12;
        g_Wt[k * DIM + d] = W[idx];
    }

    grid_barrier();

    // ---------------- Phase B: per-node stats (8 nodes / block-iter) ----------
    {
        unsigned short (*sList)[1024] = (unsigned short (*)[1024])smemBuf;  // 16 KB
        int sub = t >> 6;       // 0..7
        int d   = t & 63;
        for (int grp = blockIdx.x; grp < NN / 8; grp += GRID) {
            int n = grp * 8 + sub;

            if (d == 0) sCnt[sub] = 0;
            __syncthreads();

            if (d < 32) {
                unsigned m = g_mask[n * 32 + d];
                int base = d * 32;
                while (m) {
                    int b = __ffs(m) - 1;
                    m &= m - 1;
                    int pos = atomicAdd(&sCnt[sub], 1);
                    sList[sub][pos] = (unsigned short)(base + b);
                }
            }
            __syncthreads();

            int cnt = sCnt[sub];
            float s = 0.0f, sq = 0.0f;
            float mn = INFINITY, mx = -INFINITY;

            int j = 0;
            for (; j + 4 <= cnt; j += 4) {
                int f0 = sList[sub][j],     f1 = sList[sub][j + 1];
                int f2 = sList[sub][j + 2], f3 = sList[sub][j + 3];
                float x0 = x[f0 * DIM + d];
                float x1 = x[f1 * DIM + d];
                float x2 = x[f2 * DIM + d];
                float x3 = x[f3 * DIM + d];
                s  += (x0 + x1) + (x2 + x3);
                sq += (x0 * x0 + x1 * x1) + (x2 * x2 + x3 * x3);
                mn = fminf(mn, fminf(fminf(x0, x1), fminf(x2, x3)));
                mx = fmaxf(mx, fmaxf(fmaxf(x0, x1), fmaxf(x2, x3)));
            }
            for (; j < cnt; j++) {
                int f = sList[sub][j];
                float xv = x[f * DIM + d];
                s += xv; sq += xv * xv;
                mn = fminf(mn, xv); mx = fmaxf(mx, xv);
            }

            float deg  = (float)cnt + 1.0f;
            float mean = s / deg;
            float var  = sq / deg - mean * mean;
            float sd   = sqrtf(fmaxf(var, EPS_F));

            g_feat[n * NFEAT +           d] = mean;
            g_feat[n * NFEAT +  DIM    + d] = mn;
            g_feat[n * NFEAT + 2 * DIM + d] = mx;
            g_feat[n * NFEAT + 3 * DIM + d] = sd;
            if (d == 0) {
                float ld = logf(deg);
                g_logdeg[n] = ld;
                int b = b_n[n];
                atomicAdd(&g_bsum[b], ld);
                atomicAdd(&g_bcnt[b], 1.0f);
            }
            __syncthreads();
        }
    }

    grid_barrier();

    // ---------------- Phase C: GEMM (split-K x2) + scales + LN + ReLU ---------
    {
        float* featT = smemBuf + FEATT_OFF;   // [i][nl]   (i*16 + nl)
        float* wS    = smemBuf + WS_OFF;      // [half][3*ICH*DIM]
        float* sPart = smemBuf + SPART_OFF;   // [half][nl][acc][d]

        const int half = t >> 8;              // split-K half
        const int t2   = t & 255;
        const int d    = t2 & 63;
        const int g    = t2 >> 6;             // node quad 0..3

        for (int grp = blockIdx.x; grp < NN / NPB; grp += GRID) {
            int nb = grp * NPB;
            __syncthreads();

            // stage features transposed: featT[i*16 + nl]
            for (int k = t; k < NPB * NFEAT / 4; k += TPB) {   // 1024 float4s
                int nl = k & 15;
                int i4 = k >> 4;
                float4 f = reinterpret_cast<const float4*>(g_feat)[(nb + nl) * (NFEAT / 4) + i4];
                featT[(4 * i4 + 0) * 16 + nl] = f.x;
                featT[(4 * i4 + 1) * 16 + nl] = f.y;
                featT[(4 * i4 + 2) * 16 + nl] = f.z;
                featT[(4 * i4 + 3) * 16 + nl] = f.w;
            }

            float a0[4] = {0.f, 0.f, 0.f, 0.f};
            float a1[4] = {0.f, 0.f, 0.f, 0.f};
            float a2[4] = {0.f, 0.f, 0.f, 0.f};

            for (int step = 0; step < 4; step++) {
                __syncthreads();
                // stage both halves' current chunks (12288 floats)
                for (int k = t; k < 2 * 3 * ICH * DIM; k += TPB) {
                    int hh  = k / (3 * ICH * DIM);
                    int off = k - hh * (3 * ICH * DIM);
                    wS[k] = g_Wt[(hh * 4 + step) * (3 * ICH * DIM) + off];
                }
                __syncthreads();

                const float* wH = wS + half * (3 * ICH * DIM);
                int ibase = (half * 4 + step) * ICH;

#pragma unroll 8
                for (int il = 0; il < ICH; il++) {
                    float w0 = wH[(3 * il    ) * DIM + d];
                    float w1 = wH[(3 * il + 1) * DIM + d];
                    float w2 = wH[(3 * il + 2) * DIM + d];
                    float4 fv = *reinterpret_cast<const float4*>(
                        &featT[(ibase + il) * 16 + g * 4]);
                    a0[0] = fmaf(fv.x, w0, a0[0]);
                    a1[0] = fmaf(fv.x, w1, a1[0]);
                    a2[0] = fmaf(fv.x, w2, a2[0]);
                    a0[1] = fmaf(fv.y, w0, a0[1]);
                    a1[1] = fmaf(fv.y, w1, a1[1]);
                    a2[1] = fmaf(fv.y, w2, a2[1]);
                    a0[2] = fmaf(fv.z, w0, a0[2]);
                    a1[2] = fmaf(fv.z, w1, a1[2]);
                    a2[2] = fmaf(fv.z, w2, a2[2]);
                    a0[3] = fmaf(fv.w, w0, a0[3]);
                    a1[3] = fmaf(fv.w, w1, a1[3]);
                    a2[3] = fmaf(fv.w, w2, a2[3]);
                }
            }

            // write split-K partials
            {
                float* myP = sPart + half * (NPB * 3 * DIM);
#pragma unroll
                for (int q = 0; q < 4; q++) {
                    int nl = g * 4 + q;
                    myP[(nl * 3 + 0) * DIM + d] = a0[q];
                    myP[(nl * 3 + 1) * DIM + d] = a1[q];
                    myP[(nl * 3 + 2) * DIM + d] = a2[q];
                }
            }
            __syncthreads();

            // epilogue: warp w handles node w; lane l covers d = l and l+32
            {
                int nl = t >> 5;
                int l  = t & 31;
                int n  = nb + nl;
                int b  = b_n[n];
                float ms  = g_bsum[b] / fmaxf(g_bcnt[b], EPS_F);
                float sc  = g_logdeg[n] / fmaxf(ms, EPS_F);
                float inv = 1.0f / fmaxf(sc, EPS_F);

                const float* p0 = sPart + (nl * 3) * DIM;
                const float* p1 = p0 + NPB * 3 * DIM;

                float h[2];
#pragma unroll
                for (int u = 0; u < 2; u++) {
                    int dd = l + u * 32;
                    float c0 = p0[0 * DIM + dd] + p1[0 * DIM + dd];
                    float c1 = p0[1 * DIM + dd] + p1[1 * DIM + dd];
                    float c2 = p0[2 * DIM + dd] + p1[2 * DIM + dd];
                    h[u] = c0 + sc * c1 + inv * c2 + bias[dd];
                }

                float s1 = h[0] + h[1];
                float s2 = h[0] * h[0] + h[1] * h[1];
#pragma unroll
                for (int off = 16; off > 0; off >>= 1) {
                    s1 += __shfl_xor_sync(0xffffffffu, s1, off);
                    s2 += __shfl_xor_sync(0xffffffffu, s2, off);
                }
                float mu  = s1 * (1.0f / DIM);
                float var = s2 * (1.0f / DIM) - mu * mu;
                float rs  = rsqrtf(var + LN_EPS_F);
#pragma unroll
                for (int u = 0; u < 2; u++) {
                    int dd = l + u * 32;
                    float o = (h[u] - mu) * rs * gamma[dd] + beta[dd];
                    out[n * DIM + dd] = fmaxf(o, 0.0f);
                }
            }
        }
    }
}

// ---------------------------------------------------------------------------
extern "C" void kernel_launch(void* const* d_in, const int* in_sizes, int n_in,
                              void* d_out, int out_size) {
    const float* A     = (const float*)d_in[0];   // (1024, 2048)
    const float* x     = (const float*)d_in[1];   // (1024, 64)
    const float* W     = (const float*)d_in[2];   // (64, 768)
    const float* bias  = (const float*)d_in[3];   // (64)
    const float* gamma = (const float*)d_in[4];   // (64)
    const float* beta  = (const float*)d_in[5];   // (64)
    const int*   b_n   = (const int*)d_in[6];     // (2048)
    float* out = (float*)d_out;                   // (2048, 64)

    cudaFuncSetAttribute(fused_all, cudaFuncAttributeMaxDynamicSharedMemorySize, DYN_BYTES);
    fused_all<<<GRID, TPB, DYN_BYTES>>>(A, x, W, bias, gamma, beta, b_n, out);
}

// round 6
// speedup vs baseline: 2.0421x; 1.3333x over previous
#include <cuda_runtime.h>
#include <cuda_bf16.h>
#include <math.h>

// Problem constants (fixed by setup_inputs)
#define NF   1024
#define NN   2048
#define DIM  64
#define K12  768
#define NFEAT 256
#define EPS_F 1e-6f
#define LN_EPS_F 1e-5f

#define GRID 148       // == SM count: all blocks co-resident -> safe grid barrier
#define TPB  1024
#define NBLK 128       // node-owning blocks
#define NPB  16        // nodes per block

#define FT_STRIDE 20   // featT row stride (float4-aligned, 4-way bank conflict max)

// Dynamic smem layout (float offsets)
//   wS double buffer: [2][12288]   (2 x 48 KB)   [0, 24576)
//   sPart          : [4][16][3][64]  (48 KB)     [24576, 36864)   (phase C)
//   sList (ushort) : [16][1024]      (32 KB)     aliases sPart     (phase B)
//   sMask (uint)   : [16][32]        (2 KB)      [36864, 37376)
//   sA             : [1024][16]      (64 KB)     [40960, 57344)   (phase A)
//   featT          : [256][20]       (20 KB)     aliases sA start (phase B/C)
#define WS_OFF     0
#define SPART_OFF  24576
#define SMASK_OFF  36864
#define SA_OFF     40960
#define FEATT_OFF  40960
#define DYN_FLOATS 57344
#define DYN_BYTES  (DYN_FLOATS * 4)   // 229376 B <= 232448 limit

// Device scratch (no allocations allowed)
__device__ float g_Wt[K12 * DIM];       // W transposed (768, 64)
__device__ float g_part[NBLK * 32 * 2]; // per-block (bsum, bcnt) per batch slot

// Grid barrier (sense-reversal; state persists across graph replays)
__device__ int                   g_bar_cnt;
__device__ volatile unsigned int g_bar_gen;

__device__ __forceinline__ void grid_barrier() {
    __syncthreads();
    if (threadIdx.x == 0) {
        unsigned int gen = g_bar_gen;
        __threadfence();
        if (atomicAdd(&g_bar_cnt, 1) == GRID - 1) {
            g_bar_cnt = 0;
            __threadfence();
            g_bar_gen = gen + 1;
        } else {
            while (g_bar_gen == gen) { }
        }
    }
    __syncthreads();
}

__device__ __forceinline__ void cpa16(unsigned int smem_dst, const void* gsrc) {
    asm volatile("cp.async.cg.shared.global [%0], [%1], 16;\n" ::
                 "r"(smem_dst), "l"(gsrc));
}
#define CP_COMMIT() asm volatile("cp.async.commit_group;\n")
#define CP_WAIT(n)  asm volatile("cp.async.wait_group %0;\n" :: "n"(n))

// Stage step s of W tiles (4 K-parts x 48 rows x 64) into wS buffer (async).
__device__ __forceinline__ void stageW(int s, unsigned int dstBase, int t) {
#pragma unroll
    for (int c = t; c < 3072; c += TPB) {         // float4 units, 3 iters
        int chunk = c / 768;                       // K-part 0..3
        int off   = c - chunk * 768;
        const float4* src = reinterpret_cast<const float4*>(g_Wt)
                            + chunk * 3072 + s * 768 + off;
        cpa16(dstBase + c * 16, src);
    }
}

__global__ void __launch_bounds__(TPB, 1)
fused_all(const float* __restrict__ A,
          const float* __restrict__ x,
          const float* __restrict__ W,
          const float* __restrict__ bias,
          const float* __restrict__ gamma,
          const float* __restrict__ beta,
          const int*   __restrict__ b_n,
          float* __restrict__ out) {
    extern __shared__ float sm[];
    float*          wS    = sm + WS_OFF;
    float*          sPart = sm + SPART_OFF;
    unsigned int*   sMask = (unsigned int*)(sm + SMASK_OFF);
    unsigned short* sList = (unsigned short*)(sm + SPART_OFF);
    float*          sA    = sm + SA_OFF;
    float*          featT = sm + FEATT_OFF;

    __shared__ float sLd[NPB], sMs[32], sSc[NPB], sInv[NPB];
    __shared__ int   sBn[NPB], sCnt[NPB];

    const int t   = threadIdx.x;
    const int blk = blockIdx.x;
    const unsigned int smBase = (unsigned int)__cvta_generic_to_shared(sm);

    // ---- W transpose (all 148 blocks cooperate) ----
    {
        int idx = blk * TPB + t;
        if (idx < K12 * DIM) {
            int d = idx / K12;
            int k = idx - d * K12;
            g_Wt[k * DIM + d] = W[idx];
        }
    }

    if (blk < NBLK) {
        const int nb = blk * NPB;

        // ---- Phase A: stage this block's 16 A-columns, build masks ----
#pragma unroll
        for (int p = 0; p < 16; p++) {
            int idx = p * TPB + t;                 // idx = f*16 + n_local
            sA[idx] = A[(idx >> 4) * NN + nb + (idx & 15)];
        }
        if (t < NPB) { sBn[t] = b_n[nb + t]; }
        __syncthreads();

        if (t < 512) {
            int w  = t >> 4;                       // feature word 0..31
            int nl = t & 15;
            unsigned m = 0;
#pragma unroll
            for (int r = 0; r < 32; r++) {
                if (sA[(w * 32 + r) * 16 + nl] != 0.0f) m |= (1u << r);
            }
            sMask[nl * 32 + w] = m;
        }
        __syncthreads();

        // ---- Phase B: edge lists (warp scan, deterministic) + stats ----
        {
            int sub = t >> 6;                      // node 0..15
            int d   = t & 63;

            if (d < 32) {                          // one full warp per node
                unsigned m = sMask[sub * 32 + d];
                int c = __popc(m);
                int pre = c;
#pragma unroll
                for (int sh = 1; sh < 32; sh <<= 1) {
                    int v = __shfl_up_sync(0xffffffffu, pre, sh);
                    if ((d & 31) >= sh) pre += v;
                }
                pre -= c;                          // exclusive prefix
                if (d == 31) sCnt[sub] = pre + c;
                int base = d * 32;
                int pos = pre;
                while (m) {
                    int b = __ffs(m) - 1;
                    m &= m - 1;
                    sList[sub * 1024 + pos++] = (unsigned short)(base + b);
                }
            }
        }
        __syncthreads();

        {
            int sub = t >> 6;
            int d   = t & 63;
            int cnt = sCnt[sub];
            const unsigned short* lst = sList + sub * 1024;

            float s = 0.0f, sq = 0.0f;
            float mn = INFINITY, mx = -INFINITY;
            int j = 0;
            for (; j + 4 <= cnt; j += 4) {
                int f0 = lst[j], f1 = lst[j + 1], f2 = lst[j + 2], f3 = lst[j + 3];
                float x0 = x[f0 * DIM + d];
                float x1 = x[f1 * DIM + d];
                float x2 = x[f2 * DIM + d];
                float x3 = x[f3 * DIM + d];
                s  += (x0 + x1) + (x2 + x3);
                sq += (x0 * x0 + x1 * x1) + (x2 * x2 + x3 * x3);
                mn = fminf(mn, fminf(fminf(x0, x1), fminf(x2, x3)));
                mx = fmaxf(mx, fmaxf(fmaxf(x0, x1), fmaxf(x2, x3)));
            }
            for (; j < cnt; j++) {
                int f = lst[j];
                float xv = x[f * DIM + d];
                s += xv; sq += xv * xv;
                mn = fminf(mn, xv); mx = fmaxf(mx, xv);
            }

            float deg  = (float)cnt + 1.0f;
            float mean = s / deg;
            float var  = sq / deg - mean * mean;
            float sd   = sqrtf(fmaxf(var, EPS_F));

            __syncthreads();   // sA fully consumed; featT may now overwrite it
            featT[(          d) * FT_STRIDE + sub] = mean;
            featT[( DIM    + d) * FT_STRIDE + sub] = mn;
            featT[(2 * DIM + d) * FT_STRIDE + sub] = mx;
            featT[(3 * DIM + d) * FT_STRIDE + sub] = sd;
            if (d == 0) sLd[sub] = logf(deg);
        }
        __syncthreads();

        // per-block batch partials (plain stores; no atomics, no zero-race)
        if (t < 32) {
            float s = 0.0f, c = 0.0f;
#pragma unroll
            for (int nl = 0; nl < NPB; nl++) {
                if (sBn[nl] == t) { s += sLd[nl]; c += 1.0f; }
            }
            g_part[(blk * 32 + t) * 2]     = s;
            g_part[(blk * 32 + t) * 2 + 1] = c;
        }
    }

    grid_barrier();
    if (blk >= NBLK) return;

    // ---- prefetch W step 0 (overlaps the batch reduction) ----
    stageW(0, smBase + WS_OFF * 4, t);
    CP_COMMIT();

    if (t < 32) {
        float s = 0.0f, c = 0.0f;
#pragma unroll 8
        for (int b = 0; b < NBLK; b++) {
            float2 v = *reinterpret_cast<const float2*>(&g_part[(b * 32 + t) * 2]);
            s += v.x; c += v.y;
        }
        sMs[t] = s / fmaxf(c, EPS_F);
    }
    __syncthreads();
    if (t < NPB) {
        float ms = sMs[sBn[t]];
        float sc = sLd[t] / fmaxf(ms, EPS_F);
        sSc[t]  = sc;
        sInv[t] = 1.0f / fmaxf(sc, EPS_F);
    }

    // ---- Phase C: split-K x4 GEMM from smem, cp.async double-buffered W ----
    const int q  = t >> 8;          // K-part 0..3 (64 i-rows each)
    const int t2 = t & 255;
    const int d  = t2 & 63;
    const int g  = t2 >> 6;         // node quad 0..3

    float a0[4] = {0.f, 0.f, 0.f, 0.f};
    float a1[4] = {0.f, 0.f, 0.f, 0.f};
    float a2[4] = {0.f, 0.f, 0.f, 0.f};

    for (int s = 0; s < 4; s++) {
        __syncthreads();            // prev buffer fully consumed
        if (s < 3) {
            stageW(s + 1, smBase + (WS_OFF + ((s + 1) & 1) * 12288) * 4, t);
            CP_COMMIT();
            CP_WAIT(1);             // step s's group complete
        } else {
            CP_WAIT(0);
        }
        __syncthreads();

        const float* wH = wS + (s & 1) * 12288 + q * 3072;
        const float* fB = featT + (q * 64 + s * 16) * FT_STRIDE + g * 4;

#pragma unroll
        for (int il = 0; il < 16; il++) {
            float w0 = wH[(il * 3 + 0) * DIM + d];
            float w1 = wH[(il * 3 + 1) * DIM + d];
            float w2 = wH[(il * 3 + 2) * DIM + d];
            float4 f = *reinterpret_cast<const float4*>(fB + il * FT_STRIDE);
            a0[0] = fmaf(f.x, w0, a0[0]);
            a1[0] = fmaf(f.x, w1, a1[0]);
            a2[0] = fmaf(f.x, w2, a2[0]);
            a0[1] = fmaf(f.y, w0, a0[1]);
            a1[1] = fmaf(f.y, w1, a1[1]);
            a2[1] = fmaf(f.y, w2, a2[1]);
            a0[2] = fmaf(f.z, w0, a0[2]);
            a1[2] = fmaf(f.z, w1, a1[2]);
            a2[2] = fmaf(f.z, w2, a2[2]);
            a0[3] = fmaf(f.w, w0, a0[3]);
            a1[3] = fmaf(f.w, w1, a1[3]);
            a2[3] = fmaf(f.w, w2, a2[3]);
        }
    }

    // write split-K partials: sPart[q][nl][3][64]
    {
        float* myP = sPart + q * (NPB * 3 * DIM);
#pragma unroll
        for (int p = 0; p < 4; p++) {
            int nl = g * 4 + p;
            myP[(nl * 3 + 0) * DIM + d] = a0[p];
            myP[(nl * 3 + 1) * DIM + d] = a1[p];
            myP[(nl * 3 + 2) * DIM + d] = a2[p];
        }
    }
    __syncthreads();

    // epilogue: warp w (<16) handles node w; lane l covers d = l and l+32
    {
        int wid = t >> 5;
        int l   = t & 31;
        if (wid < NPB) {
            int nl = wid;
            int n  = blk * NPB + nl;
            float sc  = sSc[nl];
            float inv = sInv[nl];

            float h[2];
#pragma unroll
            for (int u = 0; u < 2; u++) {
                int dd = l + u * 32;
                float c0 = 0.f, c1 = 0.f, c2 = 0.f;
#pragma unroll
                for (int qq = 0; qq < 4; qq++) {
                    const float* p = sPart + qq * (NPB * 3 * DIM) + nl * 3 * DIM;
                    c0 += p[0 * DIM + dd];
                    c1 += p[1 * DIM + dd];
                    c2 += p[2 * DIM + dd];
                }
                h[u] = c0 + sc * c1 + inv * c2 + bias[dd];
            }

            float s1 = h[0] + h[1];
            float s2 = h[0] * h[0] + h[1] * h[1];
#pragma unroll
            for (int off = 16; off > 0; off >>= 1) {
                s1 += __shfl_xor_sync(0xffffffffu, s1, off);
                s2 += __shfl_xor_sync(0xffffffffu, s2, off);
            }
            float mu  = s1 * (1.0f / DIM);
            float var = s2 * (1.0f / DIM) - mu * mu;
            float rs  = rsqrtf(var + LN_EPS_F);
#pragma unroll
            for (int u = 0; u < 2; u++) {
                int dd = l + u * 32;
                float o = (h[u] - mu) * rs * gamma[dd] + beta[dd];
                out[n * DIM + dd] = fmaxf(o, 0.0f);
            }
        }
    }
}

// ---------------------------------------------------------------------------
extern "C" void kernel_launch(void* const* d_in, const int* in_sizes, int n_in,
                              void* d_out, int out_size) {
    const float* A     = (const float*)d_in[0];   // (1024, 2048)
    const float* x     = (const float*)d_in[1];   // (1024, 64)
    const float* W     = (const float*)d_in[2];   // (64, 768)
    const float* bias  = (const float*)d_in[3];   // (64)
    const float* gamma = (const float*)d_in[4];   // (64)
    const float* beta  = (const float*)d_in[5];   // (64)
    const int*   b_n   = (const int*)d_in[6];     // (2048)
    float* out = (float*)d_out;                   // (2048, 64)

    cudaFuncSetAttribute(fused_all, cudaFuncAttributeMaxDynamicSharedMemorySize, DYN_BYTES);
    fused_all<<<GRID, TPB, DYN_BYTES>>>(A, x, W, bias, gamma, beta, b_n, out);
}

// round 7
// speedup vs baseline: 2.0590x; 1.0083x over previous
#include <cuda_runtime.h>
#include <cuda_bf16.h>
#include <math.h>

// Problem constants (fixed by setup_inputs)
#define NF   1024
#define NN   2048
#define DIM  64
#define K12  768
#define NFEAT 256
#define EPS_F 1e-6f
#define LN_EPS_F 1e-5f

#define GRID 148       // == SM count: all blocks co-resident -> safe grid barrier
#define TPB  1024
#define NBLK 128       // node-owning blocks
#define NPB  16        // nodes per block

#define FT_STRIDE 20   // featT row stride (16B-aligned rows: 20*4 = 80 = 16*5)

// Dynamic smem layout (float offsets) -- phases alias disjoint lifetimes
#define WS_OFF     0                          // wS[2][12288]   96 KB
#define SPART_OFF  24576                      // sPart[4][16][3][64] 48 KB / sList alias
#define SMASK_OFF  36864                      // sMask[16][32]   2 KB
#define SA_OFF     40960                      // sA[1024][16]   64 KB  (phase A)
#define FEATT_OFF  40960                      // featT[256][20] 20 KB  (aliases sA)
#define DYN_FLOATS 57344
#define DYN_BYTES  (DYN_FLOATS * 4)           // 229376 B

// Device scratch (no allocations allowed)
__device__ float g_Wt[K12 * DIM];       // W transposed (768, 64)
__device__ float g_part[NBLK * 32 * 2]; // per-block (bsum, bcnt) per batch slot

// Grid barrier (sense-reversal; state persists across graph replays)
__device__ int                   g_bar_cnt;
__device__ volatile unsigned int g_bar_gen;

__device__ __forceinline__ void grid_barrier() {
    __syncthreads();
    if (threadIdx.x == 0) {
        unsigned int gen = g_bar_gen;
        __threadfence();
        if (atomicAdd(&g_bar_cnt, 1) == GRID - 1) {
            g_bar_cnt = 0;
            __threadfence();
            g_bar_gen = gen + 1;
        } else {
            while (g_bar_gen == gen) { }
        }
    }
    __syncthreads();
}

// ---- packed fp32x2 helpers (FFMA2: ptxas never auto-fuses; PTX-only) ----
typedef unsigned long long ull;
__device__ __forceinline__ ull pack2(float lo, float hi) {
    ull r;
    asm("mov.b64 %0, {%1, %2};" : "=l"(r) : "f"(lo), "f"(hi));
    return r;
}
__device__ __forceinline__ void unpack2(ull v, float& lo, float& hi) {
    asm("mov.b64 {%0, %1}, %2;" : "=f"(lo), "=f"(hi) : "l"(v));
}
__device__ __forceinline__ void fma2(ull& d, ull a, ull b) {
    asm("fma.rn.f32x2 %0, %1, %2, %0;" : "+l"(d) : "l"(a), "l"(b));
}

__device__ __forceinline__ void cpa16(unsigned int smem_dst, const void* gsrc) {
    asm volatile("cp.async.cg.shared.global [%0], [%1], 16;\n" ::
                 "r"(smem_dst), "l"(gsrc));
}
#define CP_COMMIT() asm volatile("cp.async.commit_group;\n")
#define CP_WAIT(n)  asm volatile("cp.async.wait_group %0;\n" :: "n"(n))

// Stage step s of W tiles (4 K-parts x 48 rows x 64) into wS buffer (async).
__device__ __forceinline__ void stageW(int s, unsigned int dstBase, int t) {
#pragma unroll
    for (int c = t; c < 3072; c += TPB) {         // float4 units, 3 iters
        int chunk = c / 768;                       // K-part 0..3
        int off   = c - chunk * 768;
        const float4* src = reinterpret_cast<const float4*>(g_Wt)
                            + chunk * 3072 + s * 768 + off;
        cpa16(dstBase + c * 16, src);
    }
}

__global__ void __launch_bounds__(TPB, 1)
fused_all(const float* __restrict__ A,
          const float* __restrict__ x,
          const float* __restrict__ W,
          const float* __restrict__ bias,
          const float* __restrict__ gamma,
          const float* __restrict__ beta,
          const int*   __restrict__ b_n,
          float* __restrict__ out) {
    extern __shared__ float sm[];
    float*          wS    = sm + WS_OFF;
    float*          sPart = sm + SPART_OFF;
    unsigned int*   sMask = (unsigned int*)(sm + SMASK_OFF);
    unsigned short* sList = (unsigned short*)(sm + SPART_OFF);
    float*          sA    = sm + SA_OFF;
    float*          featT = sm + FEATT_OFF;

    __shared__ float sLd[NPB], sMs[32], sSc[NPB], sInv[NPB];
    __shared__ int   sBn[NPB], sCnt[NPB];

    const int t   = threadIdx.x;
    const int blk = blockIdx.x;
    const unsigned int smBase = (unsigned int)__cvta_generic_to_shared(sm);

    // ---- W transpose (all 148 blocks cooperate) ----
    {
        int idx = blk * TPB + t;
        if (idx < K12 * DIM) {
            int d = idx / K12;
            int k = idx - d * K12;
            g_Wt[k * DIM + d] = W[idx];
        }
    }

    if (blk < NBLK) {
        const int nb = blk * NPB;

        // ---- Phase A: stage this block's 16 A-columns (float4), build masks ----
        {
            const float4* A4 = reinterpret_cast<const float4*>(A);
            float4*       s4 = reinterpret_cast<float4*>(sA);
            int nb4 = nb >> 2;
#pragma unroll
            for (int p = 0; p < 4; p++) {
                int idx4 = p * TPB + t;            // idx4 = f*4 + nl4
                int f    = idx4 >> 2;
                int nl4  = idx4 & 3;
                s4[f * 4 + nl4] = A4[f * (NN / 4) + nb4 + nl4];
            }
        }
        if (t < NPB) { sBn[t] = b_n[nb + t]; }
        __syncthreads();

        if (t < 512) {
            int w  = t >> 4;                       // feature word 0..31
            int nl = t & 15;
            unsigned m = 0;
#pragma unroll
            for (int r = 0; r < 32; r++) {
                if (sA[(w * 32 + r) * 16 + nl] != 0.0f) m |= (1u << r);
            }
            sMask[nl * 32 + w] = m;
        }
        __syncthreads();

        // ---- Phase B: edge lists (warp scan, deterministic) + stats ----
        {
            int sub = t >> 6;                      // node 0..15
            int d   = t & 63;

            if (d < 32) {                          // one full warp per node
                unsigned m = sMask[sub * 32 + d];
                int c = __popc(m);
                int pre = c;
#pragma unroll
                for (int sh = 1; sh < 32; sh <<= 1) {
                    int v = __shfl_up_sync(0xffffffffu, pre, sh);
                    if ((d & 31) >= sh) pre += v;
                }
                pre -= c;                          // exclusive prefix
                if (d == 31) sCnt[sub] = pre + c;
                int base = d * 32;
                int pos = pre;
                while (m) {
                    int b = __ffs(m) - 1;
                    m &= m - 1;
                    sList[sub * 1024 + pos++] = (unsigned short)(base + b);
                }
            }
        }
        __syncthreads();

        {
            int sub = t >> 6;
            int d   = t & 63;
            int cnt = sCnt[sub];
            const unsigned short* lst = sList + sub * 1024;

            float s = 0.0f, sq = 0.0f;
            float mn = INFINITY, mx = -INFINITY;
            int j = 0;
            for (; j + 4 <= cnt; j += 4) {
                int f0 = lst[j], f1 = lst[j + 1], f2 = lst[j + 2], f3 = lst[j + 3];
                float x0 = x[f0 * DIM + d];
                float x1 = x[f1 * DIM + d];
                float x2 = x[f2 * DIM + d];
                float x3 = x[f3 * DIM + d];
                s  += (x0 + x1) + (x2 + x3);
                sq += (x0 * x0 + x1 * x1) + (x2 * x2 + x3 * x3);
                mn = fminf(mn, fminf(fminf(x0, x1), fminf(x2, x3)));
                mx = fmaxf(mx, fmaxf(fmaxf(x0, x1), fmaxf(x2, x3)));
            }
            for (; j < cnt; j++) {
                int f = lst[j];
                float xv = x[f * DIM + d];
                s += xv; sq += xv * xv;
                mn = fminf(mn, xv); mx = fmaxf(mx, xv);
            }

            float deg  = (float)cnt + 1.0f;
            float mean = s / deg;
            float var  = sq / deg - mean * mean;
            float sd   = sqrtf(fmaxf(var, EPS_F));

            __syncthreads();   // sA fully consumed; featT may now overwrite it
            featT[(          d) * FT_STRIDE + sub] = mean;
            featT[( DIM    + d) * FT_STRIDE + sub] = mn;
            featT[(2 * DIM + d) * FT_STRIDE + sub] = mx;
            featT[(3 * DIM + d) * FT_STRIDE + sub] = sd;
            if (d == 0) sLd[sub] = logf(deg);
        }
        __syncthreads();

        // per-block batch partials (plain stores; no atomics, deterministic)
        if (t < 32) {
            float s = 0.0f, c = 0.0f;
#pragma unroll
            for (int nl = 0; nl < NPB; nl++) {
                if (sBn[nl] == t) { s += sLd[nl]; c += 1.0f; }
            }
            g_part[(blk * 32 + t) * 2]     = s;
            g_part[(blk * 32 + t) * 2 + 1] = c;
        }
    }

    grid_barrier();
    if (blk >= NBLK) return;

    // ---- prefetch W step 0 (overlaps the batch reduction) ----
    stageW(0, smBase + WS_OFF * 4, t);
    CP_COMMIT();

    if (t < 32) {
        float s = 0.0f, c = 0.0f;
#pragma unroll 8
        for (int b = 0; b < NBLK; b++) {
            float2 v = *reinterpret_cast<const float2*>(&g_part[(b * 32 + t) * 2]);
            s += v.x; c += v.y;
        }
        sMs[t] = s / fmaxf(c, EPS_F);
    }
    __syncthreads();
    if (t < NPB) {
        float ms = sMs[sBn[t]];
        float sc = sLd[t] / fmaxf(ms, EPS_F);
        sSc[t]  = sc;
        sInv[t] = 1.0f / fmaxf(sc, EPS_F);
    }

    // ---- Phase C: split-K x4 GEMM, f32x2-packed node pairs ----
    const int q  = t >> 8;          // K-part 0..3 (64 i-rows each)
    const int t2 = t & 255;
    const int d  = t2 & 63;
    const int g  = t2 >> 6;         // node quad 0..3

    ull a0[2] = {0ull, 0ull};       // accum[nodepair] for W0
    ull a1[2] = {0ull, 0ull};       // ... W1
    ull a2[2] = {0ull, 0ull};       // ... W2

    for (int s = 0; s < 4; s++) {
        __syncthreads();            // prev buffer fully consumed
        if (s < 3) {
            stageW(s + 1, smBase + (WS_OFF + ((s + 1) & 1) * 12288) * 4, t);
            CP_COMMIT();
            CP_WAIT(1);             // step s's group complete
        } else {
            CP_WAIT(0);
        }
        __syncthreads();

        const float* wH = wS + (s & 1) * 12288 + q * 3072;
        const float* fB = featT + (q * 64 + s * 16) * FT_STRIDE + g * 4;

#pragma unroll
        for (int il = 0; il < 16; il++) {
            float w0s = wH[(il * 3 + 0) * DIM + d];
            float w1s = wH[(il * 3 + 1) * DIM + d];
            float w2s = wH[(il * 3 + 2) * DIM + d];
            ull w0 = pack2(w0s, w0s);
            ull w1 = pack2(w1s, w1s);
            ull w2 = pack2(w2s, w2s);
            float4 f = *reinterpret_cast<const float4*>(fB + il * FT_STRIDE);
            ull f01 = pack2(f.x, f.y);
            ull f23 = pack2(f.z, f.w);
            fma2(a0[0], f01, w0);
            fma2(a1[0], f01, w1);
            fma2(a2[0], f01, w2);
            fma2(a0[1], f23, w0);
            fma2(a1[1], f23, w1);
            fma2(a2[1], f23, w2);
        }
    }

    // write split-K partials: sPart[q][nl][3][64]
    {
        float* myP = sPart + q * (NPB * 3 * DIM);
#pragma unroll
        for (int pr = 0; pr < 2; pr++) {
            float v0lo, v0hi, v1lo, v1hi, v2lo, v2hi;
            unpack2(a0[pr], v0lo, v0hi);
            unpack2(a1[pr], v1lo, v1hi);
            unpack2(a2[pr], v2lo, v2hi);
            int nl = g * 4 + pr * 2;
            myP[((nl    ) * 3 + 0) * DIM + d] = v0lo;
            myP[((nl    ) * 3 + 1) * DIM + d] = v1lo;
            myP[((nl    ) * 3 + 2) * DIM + d] = v2lo;
            myP[((nl + 1) * 3 + 0) * DIM + d] = v0hi;
            myP[((nl + 1) * 3 + 1) * DIM + d] = v1hi;
            myP[((nl + 1) * 3 + 2) * DIM + d] = v2hi;
        }
    }
    __syncthreads();

    // epilogue: warp w (<16) handles node w; lane l covers d = l and l+32
    {
        int wid = t >> 5;
        int l   = t & 31;
        if (wid < NPB) {
            int nl = wid;
            int n  = blk * NPB + nl;
            float sc  = sSc[nl];
            float inv = sInv[nl];

            float h[2];
#pragma unroll
            for (int u = 0; u < 2; u++) {
                int dd = l + u * 32;
                float c0 = 0.f, c1 = 0.f, c2 = 0.f;
#pragma unroll
                for (int qq = 0; qq < 4; qq++) {
                    const float* p = sPart + qq * (NPB * 3 * DIM) + nl * 3 * DIM;
                    c0 += p[0 * DIM + dd];
                    c1 += p[1 * DIM + dd];
                    c2 += p[2 * DIM + dd];
                }
                h[u] = c0 + sc * c1 + inv * c2 + bias[dd];
            }

            float s1 = h[0] + h[1];
            float s2 = h[0] * h[0] + h[1] * h[1];
#pragma unroll
            for (int off = 16; off > 0; off >>= 1) {
                s1 += __shfl_xor_sync(0xffffffffu, s1, off);
                s2 += __shfl_xor_sync(0xffffffffu, s2, off);
            }
            float mu  = s1 * (1.0f / DIM);
            float var = s2 * (1.0f / DIM) - mu * mu;
            float rs  = rsqrtf(var + LN_EPS_F);
#pragma unroll
            for (int u = 0; u < 2; u++) {
                int dd = l + u * 32;
                float o = (h[u] - mu) * rs * gamma[dd] + beta[dd];
                out[n * DIM + dd] = fmaxf(o, 0.0f);
            }
        }
    }
}

// ---------------------------------------------------------------------------
extern "C" void kernel_launch(void* const* d_in, const int* in_sizes, int n_in,
                              void* d_out, int out_size) {
    const float* A     = (const float*)d_in[0];   // (1024, 2048)
    const float* x     = (const float*)d_in[1];   // (1024, 64)
    const float* W     = (const float*)d_in[2];   // (64, 768)
    const float* bias  = (const float*)d_in[3];   // (64)
    const float* gamma = (const float*)d_in[4];   // (64)
    const float* beta  = (const float*)d_in[5];   // (64)
    const int*   b_n   = (const int*)d_in[6];     // (2048)
    float* out = (float*)d_out;                   // (2048, 64)

    cudaFuncSetAttribute(fused_all, cudaFuncAttributeMaxDynamicSharedMemorySize, DYN_BYTES);
    fused_all<<<GRID, TPB, DYN_BYTES>>>(A, x, W, bias, gamma, beta, b_n, out);
}

// round 8
// speedup vs baseline: 2.2242x; 1.0803x over previous
#include <cuda_runtime.h>
#include <cuda_bf16.h>
#include <math.h>

// Problem constants (fixed by setup_inputs)
#define NF   1024
#define NN   2048
#define DIM  64
#define K12  768
#define NFEAT 256
#define EPS_F 1e-6f
#define LN_EPS_F 1e-5f

#define GRID 148       // == SM count: all blocks co-resident -> safe grid barrier
#define TPB  1024
#define NBLK 128       // node-owning blocks
#define NPB  16        // nodes per block

#define FT_STRIDE 20   // featT row stride (16B-aligned rows)

// Dynamic smem layout (float offsets) -- phases alias disjoint lifetimes
#define WS_OFF     0                          // wS[2][12288]   96 KB
#define SPART_OFF  24576                      // sPart[4][16][3][64] 48 KB / sList alias
#define SMASK_OFF  36864                      // sMask[16][32]   2 KB
#define SA_OFF     40960                      // sA[1024][16]   64 KB  (phase A)
#define FEATT_OFF  40960                      // featT[256][20] 20 KB  (aliases sA)
#define DYN_FLOATS 57344
#define DYN_BYTES  (DYN_FLOATS * 4)           // 229376 B

// Device scratch (no allocations allowed)
__device__ float g_Wt[K12 * DIM];         // W transposed (768, 64)
__device__ float g_bsumT[32 * NBLK];      // [slot][block] partial sums
__device__ float g_bcntT[32 * NBLK];      // [slot][block] partial counts

// Grid barrier (sense-reversal; state persists across graph replays)
__device__ int                   g_bar_cnt;
__device__ volatile unsigned int g_bar_gen;

// ---- packed fp32x2 helpers (FFMA2 is PTX-only) ----
typedef unsigned long long ull;
__device__ __forceinline__ ull pack2(float lo, float hi) {
    ull r;
    asm("mov.b64 %0, {%1, %2};" : "=l"(r) : "f"(lo), "f"(hi));
    return r;
}
__device__ __forceinline__ void unpack2(ull v, float& lo, float& hi) {
    asm("mov.b64 {%0, %1}, %2;" : "=f"(lo), "=f"(hi) : "l"(v));
}
__device__ __forceinline__ void fma2(ull& d, ull a, ull b) {
    asm("fma.rn.f32x2 %0, %1, %2, %0;" : "+l"(d) : "l"(a), "l"(b));
}

__device__ __forceinline__ void cpa16(unsigned int smem_dst, const void* gsrc) {
    asm volatile("cp.async.cg.shared.global [%0], [%1], 16;\n" ::
                 "r"(smem_dst), "l"(gsrc));
}
#define CP_COMMIT() asm volatile("cp.async.commit_group;\n")
#define CP_WAIT(n)  asm volatile("cp.async.wait_group %0;\n" :: "n"(n))

// Stage step s of W tiles (4 K-parts x 48 rows x 64) into wS buffer (async).
__device__ __forceinline__ void stageW(int s, unsigned int dstBase, int t) {
#pragma unroll
    for (int c = t; c < 3072; c += TPB) {         // float4 units, 3 iters
        int chunk = c / 768;
        int off   = c - chunk * 768;
        const float4* src = reinterpret_cast<const float4*>(g_Wt)
                            + chunk * 3072 + s * 768 + off;
        cpa16(dstBase + c * 16, src);
    }
}

__global__ void __launch_bounds__(TPB, 1)
fused_all(const float* __restrict__ A,
          const float* __restrict__ x,
          const float* __restrict__ W,
          const float* __restrict__ bias,
          const float* __restrict__ gamma,
          const float* __restrict__ beta,
          const int*   __restrict__ b_n,
          float* __restrict__ out) {
    extern __shared__ float sm[];
    float*          wS    = sm + WS_OFF;
    float*          sPart = sm + SPART_OFF;
    unsigned int*   sMask = (unsigned int*)(sm + SMASK_OFF);
    unsigned short* sList = (unsigned short*)(sm + SPART_OFF);
    float*          sA    = sm + SA_OFF;
    float*          featT = sm + FEATT_OFF;

    __shared__ float sLd[NPB], sMs[32], sSc[NPB], sInv[NPB];
    __shared__ int   sBn[NPB], sCnt[NPB];
    __shared__ float sBias[DIM], sGam[DIM], sBet[DIM];
    __shared__ unsigned int sGen;

    const int t   = threadIdx.x;
    const int blk = blockIdx.x;
    const unsigned int smBase = (unsigned int)__cvta_generic_to_shared(sm);

    // ---- W transpose (all 148 blocks cooperate) ----
    {
        int idx = blk * TPB + t;
        if (idx < K12 * DIM) {
            int d = idx / K12;
            int k = idx - d * K12;
            g_Wt[k * DIM + d] = W[idx];
        }
    }

    if (blk >= NBLK) {
        // non-working blocks: arrive at the barrier and exit
        __syncthreads();
        if (t == 0) {
            unsigned int gen = g_bar_gen;
            __threadfence();
            if (atomicAdd(&g_bar_cnt, 1) == GRID - 1) {
                g_bar_cnt = 0;
                __threadfence();
                g_bar_gen = gen + 1;
            }
        }
        return;
    }

    const int nb = blk * NPB;

    // ---- Phase A: stage A-columns (float4), epilogue params, masks ----
    {
        const float4* A4 = reinterpret_cast<const float4*>(A);
        float4*       s4 = reinterpret_cast<float4*>(sA);
        int nb4 = nb >> 2;
#pragma unroll
        for (int p = 0; p < 4; p++) {
            int idx4 = p * TPB + t;
            int f    = idx4 >> 2;
            int nl4  = idx4 & 3;
            s4[f * 4 + nl4] = A4[f * (NN / 4) + nb4 + nl4];
        }
    }
    if (t < NPB) sBn[t] = b_n[nb + t];
    if (t >= 64 && t < 128)  sBias[t - 64]  = bias[t - 64];
    if (t >= 128 && t < 192) sGam[t - 128]  = gamma[t - 128];
    if (t >= 192 && t < 256) sBet[t - 192]  = beta[t - 192];
    __syncthreads();

    if (t < 512) {
        int w  = t >> 4;                       // feature word 0..31
        int nl = t & 15;
        unsigned m = 0;
#pragma unroll
        for (int r = 0; r < 32; r++) {
            if (sA[(w * 32 + r) * 16 + nl] != 0.0f) m |= (1u << r);
        }
        sMask[nl * 32 + w] = m;
    }
    __syncthreads();

    // ---- edge lists (warp scan, deterministic) + degree counts ----
    {
        int sub = t >> 6;                      // node 0..15
        int d   = t & 63;
        if (d < 32) {
            unsigned m = sMask[sub * 32 + d];
            int c = __popc(m);
            int pre = c;
#pragma unroll
            for (int sh = 1; sh < 32; sh <<= 1) {
                int v = __shfl_up_sync(0xffffffffu, pre, sh);
                if ((d & 31) >= sh) pre += v;
            }
            pre -= c;
            if (d == 31) sCnt[sub] = pre + c;
            int base = d * 32;
            int pos = pre;
            while (m) {
                int b = __ffs(m) - 1;
                m &= m - 1;
                sList[sub * 1024 + pos++] = (unsigned short)(base + b);
            }
        }
    }
    __syncthreads();

    if (t < NPB) sLd[t] = logf((float)sCnt[t] + 1.0f);
    __syncthreads();

    // per-block batch partials (transposed layout for coalesced reduce)
    if (t < 32) {
        float s = 0.0f, c = 0.0f;
#pragma unroll
        for (int nl = 0; nl < NPB; nl++) {
            if (sBn[nl] == t) { s += sLd[nl]; c += 1.0f; }
        }
        g_bsumT[t * NBLK + blk] = s;
        g_bcntT[t * NBLK + blk] = c;
    }

    // ---- ARRIVE (partials + W-transpose published) ----
    __syncthreads();
    if (t == 0) {
        unsigned int gen = g_bar_gen;
        sGen = gen;
        __threadfence();
        if (atomicAdd(&g_bar_cnt, 1) == GRID - 1) {
            g_bar_cnt = 0;
            __threadfence();
            g_bar_gen = gen + 1;
        }
    }

    // ---- Phase B (overlap window): x-gather stats ----
    {
        int sub = t >> 6;
        int d   = t & 63;
        int cnt = sCnt[sub];
        const unsigned short* lst = sList + sub * 1024;

        float s = 0.0f, sq = 0.0f;
        float mn = INFINITY, mx = -INFINITY;
        int j = 0;
        for (; j + 8 <= cnt; j += 8) {
            uint4 v = *reinterpret_cast<const uint4*>(lst + j);
            int f0 = v.x & 0xffff, f1 = v.x >> 16;
            int f2 = v.y & 0xffff, f3 = v.y >> 16;
            int f4 = v.z & 0xffff, f5 = v.z >> 16;
            int f6 = v.w & 0xffff, f7 = v.w >> 16;
            float x0 = x[f0 * DIM + d];
            float x1 = x[f1 * DIM + d];
            float x2 = x[f2 * DIM + d];
            float x3 = x[f3 * DIM + d];
            float x4 = x[f4 * DIM + d];
            float x5 = x[f5 * DIM + d];
            float x6 = x[f6 * DIM + d];
            float x7 = x[f7 * DIM + d];
            s  += ((x0 + x1) + (x2 + x3)) + ((x4 + x5) + (x6 + x7));
            sq += ((x0 * x0 + x1 * x1) + (x2 * x2 + x3 * x3))
                + ((x4 * x4 + x5 * x5) + (x6 * x6 + x7 * x7));
            mn = fminf(mn, fminf(fminf(fminf(x0, x1), fminf(x2, x3)),
                                 fminf(fminf(x4, x5), fminf(x6, x7))));
            mx = fmaxf(mx, fmaxf(fmaxf(fmaxf(x0, x1), fmaxf(x2, x3)),
                                 fmaxf(fmaxf(x4, x5), fmaxf(x6, x7))));
        }
        for (; j < cnt; j++) {
            int f = lst[j];
            float xv = x[f * DIM + d];
            s += xv; sq += xv * xv;
            mn = fminf(mn, xv); mx = fmaxf(mx, xv);
        }

        float deg  = (float)cnt + 1.0f;
        float mean = s / deg;
        float var  = sq / deg - mean * mean;
        float sd   = sqrtf(fmaxf(var, EPS_F));

        __syncthreads();   // sA (mask source) fully dead; featT may alias it
        featT[(          d) * FT_STRIDE + sub] = mean;
        featT[( DIM    + d) * FT_STRIDE + sub] = mn;
        featT[(2 * DIM + d) * FT_STRIDE + sub] = mx;
        featT[(3 * DIM + d) * FT_STRIDE + sub] = sd;
    }

    // ---- WAIT (other blocks' partials + g_Wt now guaranteed visible) ----
    if (t == 0) {
        while (g_bar_gen == sGen) { }
    }
    __syncthreads();
    __threadfence();

    // ---- prefetch W step 0 (overlaps the batch reduction) ----
    stageW(0, smBase + WS_OFF * 4, t);
    CP_COMMIT();

    // warp-parallel batch reduction: warp w reduces slot w
    {
        int wslot = t >> 5;
        int l     = t & 31;
        float s = 0.0f, c = 0.0f;
#pragma unroll
        for (int r = 0; r < NBLK / 32; r++) {
            int b = l + r * 32;
            s += g_bsumT[wslot * NBLK + b];
            c += g_bcntT[wslot * NBLK + b];
        }
#pragma unroll
        for (int off = 16; off > 0; off >>= 1) {
            s += __shfl_xor_sync(0xffffffffu, s, off);
            c += __shfl_xor_sync(0xffffffffu, c, off);
        }
        if (l == 0) sMs[wslot] = s / fmaxf(c, EPS_F);
    }
    __syncthreads();
    if (t < NPB) {
        float ms = sMs[sBn[t]];
        float sc = sLd[t] / fmaxf(ms, EPS_F);
        sSc[t]  = sc;
        sInv[t] = 1.0f / fmaxf(sc, EPS_F);
    }

    // ---- Phase C: split-K x4 GEMM, f32x2-packed node pairs ----
    const int q  = t >> 8;          // K-part 0..3 (64 i-rows each)
    const int t2 = t & 255;
    const int d  = t2 & 63;
    const int g  = t2 >> 6;         // node quad 0..3

    ull a0[2] = {0ull, 0ull};
    ull a1[2] = {0ull, 0ull};
    ull a2[2] = {0ull, 0ull};

    for (int s = 0; s < 4; s++) {
        __syncthreads();
        if (s < 3) {
            stageW(s + 1, smBase + (WS_OFF + ((s + 1) & 1) * 12288) * 4, t);
            CP_COMMIT();
            CP_WAIT(1);
        } else {
            CP_WAIT(0);
        }
        __syncthreads();

        const float* wH = wS + (s & 1) * 12288 + q * 3072;
        const float* fB = featT + (q * 64 + s * 16) * FT_STRIDE + g * 4;

#pragma unroll
        for (int il = 0; il < 16; il++) {
            float w0s = wH[(il * 3 + 0) * DIM + d];
            float w1s = wH[(il * 3 + 1) * DIM + d];
            float w2s = wH[(il * 3 + 2) * DIM + d];
            ull w0 = pack2(w0s, w0s);
            ull w1 = pack2(w1s, w1s);
            ull w2 = pack2(w2s, w2s);
            float4 f = *reinterpret_cast<const float4*>(fB + il * FT_STRIDE);
            ull f01 = pack2(f.x, f.y);
            ull f23 = pack2(f.z, f.w);
            fma2(a0[0], f01, w0);
            fma2(a1[0], f01, w1);
            fma2(a2[0], f01, w2);
            fma2(a0[1], f23, w0);
            fma2(a1[1], f23, w1);
            fma2(a2[1], f23, w2);
        }
    }

    // write split-K partials: sPart[q][nl][3][64]
    {
        float* myP = sPart + q * (NPB * 3 * DIM);
#pragma unroll
        for (int pr = 0; pr < 2; pr++) {
            float v0lo, v0hi, v1lo, v1hi, v2lo, v2hi;
            unpack2(a0[pr], v0lo, v0hi);
            unpack2(a1[pr], v1lo, v1hi);
            unpack2(a2[pr], v2lo, v2hi);
            int nl = g * 4 + pr * 2;
            myP[((nl    ) * 3 + 0) * DIM + d] = v0lo;
            myP[((nl    ) * 3 + 1) * DIM + d] = v1lo;
            myP[((nl    ) * 3 + 2) * DIM + d] = v2lo;
            myP[((nl + 1) * 3 + 0) * DIM + d] = v0hi;
            myP[((nl + 1) * 3 + 1) * DIM + d] = v1hi;
            myP[((nl + 1) * 3 + 2) * DIM + d] = v2hi;
        }
    }
    __syncthreads();

    // epilogue: warp w (<16) handles node w; lane l covers d = l and l+32
    {
        int wid = t >> 5;
        int l   = t & 31;
        if (wid < NPB) {
            int nl = wid;
            int n  = blk * NPB + nl;
            float sc  = sSc[nl];
            float inv = sInv[nl];

            float h[2];
#pragma unroll
            for (int u = 0; u < 2; u++) {
                int dd = l + u * 32;
                float c0 = 0.f, c1 = 0.f, c2 = 0.f;
#pragma unroll
                for (int qq = 0; qq < 4; qq++) {
                    const float* p = sPart + qq * (NPB * 3 * DIM) + nl * 3 * DIM;
                    c0 += p[0 * DIM + dd];
                    c1 += p[1 * DIM + dd];
                    c2 += p[2 * DIM + dd];
                }
                h[u] = c0 + sc * c1 + inv * c2 + sBias[dd];
            }

            float s1 = h[0] + h[1];
            float s2 = h[0] * h[0] + h[1] * h[1];
#pragma unroll
            for (int off = 16; off > 0; off >>= 1) {
                s1 += __shfl_xor_sync(0xffffffffu, s1, off);
                s2 += __shfl_xor_sync(0xffffffffu, s2, off);
            }
            float mu  = s1 * (1.0f / DIM);
            float var = s2 * (1.0f / DIM) - mu * mu;
            float rs  = rsqrtf(var + LN_EPS_F);
#pragma unroll
            for (int u = 0; u < 2; u++) {
                int dd = l + u * 32;
                float o = (h[u] - mu) * rs * sGam[dd] + sBet[dd];
                out[n * DIM + dd] = fmaxf(o, 0.0f);
            }
        }
    }
}

// ---------------------------------------------------------------------------
extern "C" void kernel_launch(void* const* d_in, const int* in_sizes, int n_in,
                              void* d_out, int out_size) {
    const float* A     = (const float*)d_in[0];   // (1024, 2048)
    const float* x     = (const float*)d_in[1];   // (1024, 64)
    const float* W     = (const float*)d_in[2];   // (64, 768)
    const float* bias  = (const float*)d_in[3];   // (64)
    const float* gamma = (const float*)d_in[4];   // (64)
    const float* beta  = (const float*)d_in[5];   // (64)
    const int*   b_n   = (const int*)d_in[6];     // (2048)
    float* out = (float*)d_out;                   // (2048, 64)

    cudaFuncSetAttribute(fused_all, cudaFuncAttributeMaxDynamicSharedMemorySize, DYN_BYTES);
    fused_all<<<GRID, TPB, DYN_BYTES>>>(A, x, W, bias, gamma, beta, b_n, out);
}